// round 7
// baseline (speedup 1.0000x reference)
#include <cuda_runtime.h>
#include <cuda_bf16.h>
#include <cstdint>

// S4 kernel materialization on HMMA (mma.sync m16n8k16 bf16):
//   K[h,l] = 2*Re( sum_n Cc_n z_n^l ),  z = exp(dtA), Cc = C*(z-1)/A
// l = 64q + r -> per-h GEMM D[64q][64r] = A[64x64] @ B[64x64]^T (K=64, j=2n re/im)
//   A row q: word n = (Re z^(64q), Im z^(64q)); B row r: word n = (2Re, -2Im) Cc z^r
// bf16 hi/lo 3-product split (explicit): D = Ahi*Bhi + Ahi*Blo + Alo*Bhi.
// Tiles built directly by 128-thread geometric chains (no anchor smem).

#define Hh   1024
#define NHn  32
#define Ll   4096

__device__ __forceinline__ uint32_t split_pack(float re, float im, uint32_t& lo_out) {
    __nv_bfloat16 hr = __float2bfloat16_rn(re);
    __nv_bfloat16 hm = __float2bfloat16_rn(im);
    float lr = re - __bfloat162float(hr);
    float lm = im - __bfloat162float(hm);
    __nv_bfloat16 lr16 = __float2bfloat16_rn(lr);
    __nv_bfloat16 lm16 = __float2bfloat16_rn(lm);
    lo_out = ((uint32_t)__bfloat16_as_ushort(lm16) << 16) | __bfloat16_as_ushort(lr16);
    return  ((uint32_t)__bfloat16_as_ushort(hm)   << 16) | __bfloat16_as_ushort(hr);
}

__device__ __forceinline__ void mma16816(float* c, const uint32_t* a,
                                         uint32_t b0, uint32_t b1) {
    asm volatile(
        "mma.sync.aligned.m16n8k16.row.col.f32.bf16.bf16.f32 "
        "{%0,%1,%2,%3}, {%4,%5,%6,%7}, {%8,%9}, {%0,%1,%2,%3};"
        : "+f"(c[0]), "+f"(c[1]), "+f"(c[2]), "+f"(c[3])
        : "r"(a[0]), "r"(a[1]), "r"(a[2]), "r"(a[3]), "r"(b0), "r"(b1));
}

__global__ __launch_bounds__(128, 6)
void s4_hmma_kernel(const float* __restrict__ Cin,        // [H, NH, 2]
                    const float* __restrict__ log_dt,     // [H]
                    const float* __restrict__ log_A_real, // [H, NH]
                    const float* __restrict__ A_imag,     // [H, NH]
                    float* __restrict__ out)              // [H, L]
{
    // 64 rows x 32 words (64 bf16) per tile, XOR swizzle: word = n ^ ((row&7)<<2)
    __shared__ uint32_t Ahi[64 * 32], Alo[64 * 32];
    __shared__ uint32_t Bhi[64 * 32], Blo[64 * 32];

    const int h    = blockIdx.x;
    const int tid  = threadIdx.x;
    const int lane = tid & 31;
    const int w    = tid >> 5;

    // ---- phase 1: all 128 threads build tiles via geometric chains ----
    {
        const int n    = lane;
        const int role = w;          // 0,1 -> B rows; 2,3 -> A rows

        float dt   = expf(log_dt[h]);
        float Are  = -expf(log_A_real[h * NHn + n]);
        float Aim  = -A_imag[h * NHn + n];
        float dtar = Are * dt;
        float dtai = Aim * dt;

        float er = expf(dtar);
        float sn, cs;
        sincosf(dtai, &sn, &cs);
        float zr = er * cs, zi = er * sn;            // z = exp(dtA)

        // Cc = C * (z-1)/A
        float nr = zr - 1.0f, ni = zi;
        float inv = 1.0f / (Are * Are + Aim * Aim);
        float fr = (nr * Are + ni * Aim) * inv;
        float fi = (ni * Are - nr * Aim) * inv;
        float c0 = Cin[(h * NHn + n) * 2 + 0];
        float c1 = Cin[(h * NHn + n) * 2 + 1];
        float ccr = c0 * fr - c1 * fi;
        float cci = c0 * fi + c1 * fr;

        // squarings: z^32, z^64, z^2048
        float sqr = zr, sqi = zi;
        #pragma unroll
        for (int s = 0; s < 5; s++) { float t = sqr*sqr - sqi*sqi; sqi = 2.0f*sqr*sqi; sqr = t; }
        float z32r = sqr, z32i = sqi;
        { float t = sqr*sqr - sqi*sqi; sqi = 2.0f*sqr*sqi; sqr = t; }
        float z64r = sqr, z64i = sqi;
        #pragma unroll
        for (int s = 0; s < 5; s++) { float t = sqr*sqr - sqi*sqi; sqi = 2.0f*sqr*sqi; sqr = t; }
        float z2048r = sqr, z2048i = sqi;

        // per-role start / step / destination
        float pr, pi, str, sti;
        bool  isB;
        if (role == 0)      { pr = ccr; pi = cci; str = zr; sti = zi; isB = true;  }
        else if (role == 1) { pr = ccr * z32r - cci * z32i;
                              pi = ccr * z32i + cci * z32r;
                              str = zr; sti = zi; isB = true;  }
        else if (role == 2) { pr = 1.0f; pi = 0.0f; str = z64r; sti = z64i; isB = false; }
        else                { pr = z2048r; pi = z2048i; str = z64r; sti = z64i; isB = false; }

        uint32_t* thi = isB ? Bhi : Ahi;
        uint32_t* tlo = isB ? Blo : Alo;
        const float foldr = isB ?  2.0f : 1.0f;
        const float foldi = isB ? -2.0f : 1.0f;
        const int   row0  = (role & 1) * 32;

        #pragma unroll 8
        for (int i = 0; i < 32; i++) {
            int row = row0 + i;
            int wo  = row * 32 + (n ^ ((row & 7) << 2));
            uint32_t lo, hi = split_pack(foldr * pr, foldi * pi, lo);
            thi[wo] = hi;
            tlo[wo] = lo;
            float t = pr * str - pi * sti;
            pi = pr * sti + pi * str;
            pr = t;
        }
    }
    __syncthreads();

    // ---- phase 2: MMA. warp w owns q rows [16w, 16w+16) (verified R5 layout) ----
    const int lane4 = lane >> 2;          // 0..7
    const int kq    = lane & 3;           // 0..3
    const int xr    = lane4 << 2;
    const int rowA0 = w * 16 + lane4;

    float acc[8][4];
    #pragma unroll
    for (int nt = 0; nt < 8; nt++)
        #pragma unroll
        for (int i = 0; i < 4; i++) acc[nt][i] = 0.0f;

    #pragma unroll
    for (int ks = 0; ks < 4; ks++) {
        int wc0 = ks * 8 + kq;            // word col of k element pair
        int wc1 = wc0 + 4;                // +8 k elements
        int o00 = rowA0 * 32 + (wc0 ^ xr);
        int o10 = (rowA0 + 8) * 32 + (wc0 ^ xr);
        int o01 = rowA0 * 32 + (wc1 ^ xr);
        int o11 = (rowA0 + 8) * 32 + (wc1 ^ xr);
        uint32_t ah[4] = { Ahi[o00], Ahi[o10], Ahi[o01], Ahi[o11] };
        uint32_t al[4] = { Alo[o00], Alo[o10], Alo[o01], Alo[o11] };

        #pragma unroll
        for (int nt = 0; nt < 8; nt++) {
            int rowB = nt * 8 + lane4;
            int ob0  = rowB * 32 + (wc0 ^ xr);
            int ob1  = rowB * 32 + (wc1 ^ xr);
            uint32_t bh0 = Bhi[ob0], bh1 = Bhi[ob1];
            uint32_t bl0 = Blo[ob0], bl1 = Blo[ob1];
            mma16816(acc[nt], ah, bh0, bh1);
            mma16816(acc[nt], ah, bl0, bl1);
            mma16816(acc[nt], al, bh0, bh1);
        }
    }

    // ---- epilogue: D(q, r) -> out[h, 64q + r] ----
    float* o = out + (size_t)h * Ll;
    const int q0 = rowA0, q1 = rowA0 + 8;
    const int cb = kq * 2;
    #pragma unroll
    for (int nt = 0; nt < 8; nt++) {
        int c = nt * 8 + cb;
        *(float2*)&o[q0 * 64 + c] = make_float2(acc[nt][0], acc[nt][1]);
        *(float2*)&o[q1 * 64 + c] = make_float2(acc[nt][2], acc[nt][3]);
    }
}

extern "C" void kernel_launch(void* const* d_in, const int* in_sizes, int n_in,
                              void* d_out, int out_size)
{
    const float* C          = (const float*)d_in[0];   // [H, NH, 2]
    const float* log_dt     = (const float*)d_in[1];   // [H]
    const float* log_A_real = (const float*)d_in[2];   // [H, NH]
    const float* A_imag     = (const float*)d_in[3];   // [H, NH]
    float* out              = (float*)d_out;           // [H, L]

    s4_hmma_kernel<<<Hh, 128>>>(C, log_dt, log_A_real, A_imag, out);
}

// round 8
// speedup vs baseline: 1.1626x; 1.1626x over previous
#include <cuda_runtime.h>
#include <cuda_fp16.h>
#include <cstdint>

// S4 kernel materialization on HMMA (mma.sync m16n8k16 fp16):
//   K[h,l] = 2*Re( sum_n Cc_n z_n^l ),  z = exp(dtA), Cc = C*(z-1)/A
// l = 64q + r -> per-h GEMM D[64q][64r] = A[64x64] @ B[64x64]^T (K=64, j=2n re/im)
//   A row q: word n = (Re z^(64q), Im z^(64q))  -- fp16 hi/lo SPLIT (2 tiles)
//   B row r: word n = (2Re, -2Im) of Cc z^r     -- single fp16 tile
// D = Ahi*B + Alo*B  (fp32 accum). B-rounding error ~2^-12 ~ 2e-4 rel.

#define Hh   1024
#define NHn  32
#define Ll   4096

__device__ __forceinline__ uint32_t pack_h2(float re, float im) {
    __half2 v = __floats2half2_rn(re, im);   // low = re (k even), high = im (k odd)
    return *(uint32_t*)&v;
}

__device__ __forceinline__ void split_h2(float re, float im, uint32_t& hi, uint32_t& lo) {
    __half hr = __float2half_rn(re);
    __half hm = __float2half_rn(im);
    float lr = re - __half2float(hr);
    float lm = im - __half2float(hm);
    __half2 hv; hv.x = hr; hv.y = hm;
    hi = *(uint32_t*)&hv;
    lo = pack_h2(lr, lm);
}

__device__ __forceinline__ void mma16816(float* c, const uint32_t* a,
                                         uint32_t b0, uint32_t b1) {
    asm volatile(
        "mma.sync.aligned.m16n8k16.row.col.f32.f16.f16.f32 "
        "{%0,%1,%2,%3}, {%4,%5,%6,%7}, {%8,%9}, {%0,%1,%2,%3};"
        : "+f"(c[0]), "+f"(c[1]), "+f"(c[2]), "+f"(c[3])
        : "r"(a[0]), "r"(a[1]), "r"(a[2]), "r"(a[3]), "r"(b0), "r"(b1));
}

__global__ __launch_bounds__(128, 8)
void s4_hmma_kernel(const float* __restrict__ Cin,        // [H, NH, 2]
                    const float* __restrict__ log_dt,     // [H]
                    const float* __restrict__ log_A_real, // [H, NH]
                    const float* __restrict__ A_imag,     // [H, NH]
                    float* __restrict__ out)              // [H, L]
{
    // 64 rows x 32 words (64 fp16) per tile, XOR swizzle: word = n ^ ((row&7)<<2)
    __shared__ uint32_t Ahi[64 * 32], Alo[64 * 32];
    __shared__ uint32_t Bt[64 * 32];

    const int h    = blockIdx.x;
    const int tid  = threadIdx.x;
    const int lane = tid & 31;
    const int w    = tid >> 5;

    // ---- phase 1: all 128 threads build tiles via geometric chains ----
    {
        const int n    = lane;
        const int role = w;          // 0,1 -> B rows; 2,3 -> A rows

        float dt   = expf(log_dt[h]);
        float Are  = -expf(log_A_real[h * NHn + n]);
        float Aim  = -A_imag[h * NHn + n];
        float dtar = Are * dt;
        float dtai = Aim * dt;

        float er = expf(dtar);
        float sn, cs;
        sincosf(dtai, &sn, &cs);
        float zr = er * cs, zi = er * sn;            // z = exp(dtA)

        // Cc = C * (z-1)/A
        float nr = zr - 1.0f, ni = zi;
        float inv = 1.0f / (Are * Are + Aim * Aim);
        float fr = (nr * Are + ni * Aim) * inv;
        float fi = (ni * Are - nr * Aim) * inv;
        float c0 = Cin[(h * NHn + n) * 2 + 0];
        float c1 = Cin[(h * NHn + n) * 2 + 1];
        float ccr = c0 * fr - c1 * fi;
        float cci = c0 * fi + c1 * fr;

        // squarings: z^32, z^64, z^2048
        float sqr = zr, sqi = zi;
        #pragma unroll
        for (int s = 0; s < 5; s++) { float t = sqr*sqr - sqi*sqi; sqi = 2.0f*sqr*sqi; sqr = t; }
        float z32r = sqr, z32i = sqi;
        { float t = sqr*sqr - sqi*sqi; sqi = 2.0f*sqr*sqi; sqr = t; }
        float z64r = sqr, z64i = sqi;
        #pragma unroll
        for (int s = 0; s < 5; s++) { float t = sqr*sqr - sqi*sqi; sqi = 2.0f*sqr*sqi; sqr = t; }
        float z2048r = sqr, z2048i = sqi;

        if (role < 2) {
            // B rows: row = 32*role + i, value = Cc * z^row, fold (2, -2)
            float pr, pi;
            if (role == 0) { pr = ccr; pi = cci; }
            else           { pr = ccr * z32r - cci * z32i;
                             pi = ccr * z32i + cci * z32r; }
            const int row0 = role * 32;
            #pragma unroll 8
            for (int i = 0; i < 32; i++) {
                int row = row0 + i;
                Bt[row * 32 + (n ^ ((row & 7) << 2))] = pack_h2(2.0f * pr, -2.0f * pi);
                float t = pr * zr - pi * zi;
                pi = pr * zi + pi * zr;
                pr = t;
            }
        } else {
            // A rows: row = 32*(role-2) + i, value = z^(64*row), split hi/lo
            float pr, pi;
            if (role == 2) { pr = 1.0f;    pi = 0.0f;    }
            else           { pr = z2048r;  pi = z2048i;  }
            const int row0 = (role - 2) * 32;
            #pragma unroll 8
            for (int i = 0; i < 32; i++) {
                int row = row0 + i;
                int wo  = row * 32 + (n ^ ((row & 7) << 2));
                uint32_t hi, lo;
                split_h2(pr, pi, hi, lo);
                Ahi[wo] = hi;
                Alo[wo] = lo;
                float t = pr * z64r - pi * z64i;
                pi = pr * z64i + pi * z64r;
                pr = t;
            }
        }
    }
    __syncthreads();

    // ---- phase 2: MMA. warp w owns q rows [16w, 16w+16) (verified layout) ----
    const int lane4 = lane >> 2;          // 0..7
    const int kq    = lane & 3;           // 0..3
    const int xr    = lane4 << 2;
    const int rowA0 = w * 16 + lane4;

    float acc[8][4];
    #pragma unroll
    for (int nt = 0; nt < 8; nt++)
        #pragma unroll
        for (int i = 0; i < 4; i++) acc[nt][i] = 0.0f;

    #pragma unroll
    for (int ks = 0; ks < 4; ks++) {
        int wc0 = ks * 8 + kq;            // word col of k element pair
        int wc1 = wc0 + 4;                // +8 k elements
        int o00 = rowA0 * 32 + (wc0 ^ xr);
        int o10 = (rowA0 + 8) * 32 + (wc0 ^ xr);
        int o01 = rowA0 * 32 + (wc1 ^ xr);
        int o11 = (rowA0 + 8) * 32 + (wc1 ^ xr);
        uint32_t ah[4] = { Ahi[o00], Ahi[o10], Ahi[o01], Ahi[o11] };
        uint32_t al[4] = { Alo[o00], Alo[o10], Alo[o01], Alo[o11] };

        #pragma unroll
        for (int nt = 0; nt < 8; nt++) {
            int rowB = nt * 8 + lane4;
            int ob0  = rowB * 32 + (wc0 ^ xr);
            int ob1  = rowB * 32 + (wc1 ^ xr);
            uint32_t b0 = Bt[ob0], b1 = Bt[ob1];
            mma16816(acc[nt], ah, b0, b1);
            mma16816(acc[nt], al, b0, b1);
        }
    }

    // ---- epilogue: D(q, r) -> out[h, 64q + r] ----
    float* o = out + (size_t)h * Ll;
    const int q0 = rowA0, q1 = rowA0 + 8;
    const int cb = kq * 2;
    #pragma unroll
    for (int nt = 0; nt < 8; nt++) {
        int c = nt * 8 + cb;
        *(float2*)&o[q0 * 64 + c] = make_float2(acc[nt][0], acc[nt][1]);
        *(float2*)&o[q1 * 64 + c] = make_float2(acc[nt][2], acc[nt][3]);
    }
}

extern "C" void kernel_launch(void* const* d_in, const int* in_sizes, int n_in,
                              void* d_out, int out_size)
{
    const float* C          = (const float*)d_in[0];   // [H, NH, 2]
    const float* log_dt     = (const float*)d_in[1];   // [H]
    const float* log_A_real = (const float*)d_in[2];   // [H, NH]
    const float* A_imag     = (const float*)d_in[3];   // [H, NH]
    float* out              = (float*)d_out;           // [H, L]

    s4_hmma_kernel<<<Hh, 128>>>(C, log_dt, log_A_real, A_imag, out);
}

// round 9
// speedup vs baseline: 1.4090x; 1.2119x over previous
#include <cuda_runtime.h>
#include <cuda_fp16.h>
#include <cstdint>

// S4 kernel materialization on HMMA (mma.sync m16n8k16 fp16):
//   K[h,l] = 2*Re( sum_n Cc_n z_n^l ),  z = exp(dtA), Cc = C*(z-1)/A
// l = 64q + r -> per-h GEMM D[64q][64r] = A[64x64] @ B[64x64]^T (K=64, j=2n re/im)
//   A row q: word n = (Re z^(64q), Im z^(64q))  -- fp16 hi/lo SPLIT (2 tiles)
//   B row r: word n = (2Re, -2Im) of Cc z^r     -- single fp16 tile
// D = Ahi*B + Alo*B  (fp32 accum).
// Phase 1: every warp runs 4 balanced chains of length 8 (2 B rows-of-16 +
// 2 A rows-of-16) -> 4x shorter dependency chain, zero warp imbalance.

#define Hh   1024
#define NHn  32
#define Ll   4096

__device__ __forceinline__ uint32_t pack_h2(float re, float im) {
    __half2 v = __floats2half2_rn(re, im);   // low = re (k even), high = im (k odd)
    return *(uint32_t*)&v;
}

__device__ __forceinline__ void split_h2(float re, float im, uint32_t& hi, uint32_t& lo) {
    __half hr = __float2half_rn(re);
    __half hm = __float2half_rn(im);
    float lr = re - __half2float(hr);
    float lm = im - __half2float(hm);
    __half2 hv; hv.x = hr; hv.y = hm;
    hi = *(uint32_t*)&hv;
    lo = pack_h2(lr, lm);
}

__device__ __forceinline__ void mma16816(float* c, const uint32_t* a,
                                         uint32_t b0, uint32_t b1) {
    asm volatile(
        "mma.sync.aligned.m16n8k16.row.col.f32.f16.f16.f32 "
        "{%0,%1,%2,%3}, {%4,%5,%6,%7}, {%8,%9}, {%0,%1,%2,%3};"
        : "+f"(c[0]), "+f"(c[1]), "+f"(c[2]), "+f"(c[3])
        : "r"(a[0]), "r"(a[1]), "r"(a[2]), "r"(a[3]), "r"(b0), "r"(b1));
}

__global__ __launch_bounds__(128, 8)
void s4_hmma_kernel(const float* __restrict__ Cin,        // [H, NH, 2]
                    const float* __restrict__ log_dt,     // [H]
                    const float* __restrict__ log_A_real, // [H, NH]
                    const float* __restrict__ A_imag,     // [H, NH]
                    float* __restrict__ out)              // [H, L]
{
    // 64 rows x 32 words (64 fp16) per tile, XOR swizzle: word = n ^ ((row&7)<<2)
    __shared__ uint32_t Ahi[64 * 32], Alo[64 * 32];
    __shared__ uint32_t Bt[64 * 32];

    const int h    = blockIdx.x;
    const int tid  = threadIdx.x;
    const int lane = tid & 31;
    const int w    = tid >> 5;

    // ---- phase 1: 4 chains x 8 steps per warp, perfectly balanced ----
    {
        const int n = lane;

        float dt   = expf(log_dt[h]);
        float Are  = -expf(log_A_real[h * NHn + n]);
        float Aim  = -A_imag[h * NHn + n];
        float dtar = Are * dt;
        float dtai = Aim * dt;

        float er = expf(dtar);
        float sn, cs;
        sincosf(dtai, &sn, &cs);
        float zr = er * cs, zi = er * sn;            // z = exp(dtA)

        // Cc = C * (z-1)/A
        float nr = zr - 1.0f, ni = zi;
        float inv = 1.0f / (Are * Are + Aim * Aim);
        float fr = (nr * Are + ni * Aim) * inv;
        float fi = (ni * Are - nr * Aim) * inv;
        float c0 = Cin[(h * NHn + n) * 2 + 0];
        float c1 = Cin[(h * NHn + n) * 2 + 1];
        float ccr = c0 * fr - c1 * fi;
        float cci = c0 * fi + c1 * fr;

        // anchors by repeated squaring
        #define CSQ(r_, i_) { float t_ = r_*r_ - i_*i_; i_ = 2.0f*r_*i_; r_ = t_; }
        float z8r = zr, z8i = zi;
        CSQ(z8r, z8i) CSQ(z8r, z8i) CSQ(z8r, z8i)               // z^8
        float z16r = z8r, z16i = z8i;  CSQ(z16r, z16i)          // z^16
        float z32r = z16r, z32i = z16i; CSQ(z32r, z32i)         // z^32
        float z64r = z32r, z64i = z32i; CSQ(z64r, z64i)         // z^64
        float z512r = z64r, z512i = z64i;
        CSQ(z512r, z512i) CSQ(z512r, z512i) CSQ(z512r, z512i)   // z^512
        float z1024r = z512r, z1024i = z512i; CSQ(z1024r, z1024i)   // z^1024
        float z2048r = z1024r, z2048i = z1024i; CSQ(z2048r, z2048i) // z^2048
        #undef CSQ

        // z^(16w): {1, z16, z32, z16*z32}
        float pwr, pwi;
        if (w == 0)      { pwr = 1.0f;  pwi = 0.0f;  }
        else if (w == 1) { pwr = z16r;  pwi = z16i;  }
        else if (w == 2) { pwr = z32r;  pwi = z32i;  }
        else             { pwr = z16r * z32r - z16i * z32i;
                           pwi = z16r * z32i + z16i * z32r; }

        // z^(1024w): {1, z1024, z2048, z1024*z2048}
        float awr, awi;
        if (w == 0)      { awr = 1.0f;   awi = 0.0f;   }
        else if (w == 1) { awr = z1024r; awi = z1024i; }
        else if (w == 2) { awr = z2048r; awi = z2048i; }
        else             { awr = z1024r * z2048r - z1024i * z2048i;
                           awi = z1024r * z2048i + z1024i * z2048r; }

        // chain starts
        float s0r = ccr * pwr - cci * pwi;           // B row 16w   : Cc z^(16w)
        float s0i = ccr * pwi + cci * pwr;
        float s1r = s0r * z8r - s0i * z8i;           // B row 16w+8 : Cc z^(16w+8)
        float s1i = s0r * z8i + s0i * z8r;
        float t0r = awr, t0i = awi;                  // A row 16w   : z^(1024w)
        float t1r = awr * z512r - awi * z512i;       // A row 16w+8 : z^(1024w+512)
        float t1i = awr * z512i + awi * z512r;

        const int rowB0 = w * 16, rowB1 = w * 16 + 8;
        const int rowA0 = w * 16, rowA1 = w * 16 + 8;

        #pragma unroll
        for (int i = 0; i < 8; i++) {
            int rb0 = rowB0 + i, rb1 = rowB1 + i;
            int ra0 = rowA0 + i, ra1 = rowA1 + i;
            Bt[rb0 * 32 + (n ^ ((rb0 & 7) << 2))] = pack_h2(2.0f * s0r, -2.0f * s0i);
            Bt[rb1 * 32 + (n ^ ((rb1 & 7) << 2))] = pack_h2(2.0f * s1r, -2.0f * s1i);
            uint32_t hi, lo;
            split_h2(t0r, t0i, hi, lo);
            { int wo = ra0 * 32 + (n ^ ((ra0 & 7) << 2)); Ahi[wo] = hi; Alo[wo] = lo; }
            split_h2(t1r, t1i, hi, lo);
            { int wo = ra1 * 32 + (n ^ ((ra1 & 7) << 2)); Ahi[wo] = hi; Alo[wo] = lo; }

            float t;
            t = s0r * zr - s0i * zi;     s0i = s0r * zi + s0i * zr;     s0r = t;
            t = s1r * zr - s1i * zi;     s1i = s1r * zi + s1i * zr;     s1r = t;
            t = t0r * z64r - t0i * z64i; t0i = t0r * z64i + t0i * z64r; t0r = t;
            t = t1r * z64r - t1i * z64i; t1i = t1r * z64i + t1i * z64r; t1r = t;
        }
    }
    __syncthreads();

    // ---- phase 2: MMA. warp w owns q rows [16w, 16w+16) (verified layout) ----
    const int lane4 = lane >> 2;          // 0..7
    const int kq    = lane & 3;           // 0..3
    const int xr    = lane4 << 2;
    const int rowA0 = w * 16 + lane4;

    float acc[8][4];
    #pragma unroll
    for (int nt = 0; nt < 8; nt++)
        #pragma unroll
        for (int i = 0; i < 4; i++) acc[nt][i] = 0.0f;

    #pragma unroll
    for (int ks = 0; ks < 4; ks++) {
        int wc0 = ks * 8 + kq;            // word col of k element pair
        int wc1 = wc0 + 4;                // +8 k elements
        int o00 = rowA0 * 32 + (wc0 ^ xr);
        int o10 = (rowA0 + 8) * 32 + (wc0 ^ xr);
        int o01 = rowA0 * 32 + (wc1 ^ xr);
        int o11 = (rowA0 + 8) * 32 + (wc1 ^ xr);
        uint32_t ah[4] = { Ahi[o00], Ahi[o10], Ahi[o01], Ahi[o11] };
        uint32_t al[4] = { Alo[o00], Alo[o10], Alo[o01], Alo[o11] };

        #pragma unroll
        for (int nt = 0; nt < 8; nt++) {
            int rowB = nt * 8 + lane4;
            int ob0  = rowB * 32 + (wc0 ^ xr);
            int ob1  = rowB * 32 + (wc1 ^ xr);
            uint32_t b0 = Bt[ob0], b1 = Bt[ob1];
            mma16816(acc[nt], ah, b0, b1);
            mma16816(acc[nt], al, b0, b1);
        }
    }

    // ---- epilogue: D(q, r) -> out[h, 64q + r] ----
    float* o = out + (size_t)h * Ll;
    const int q0 = rowA0, q1 = rowA0 + 8;
    const int cb = kq * 2;
    #pragma unroll
    for (int nt = 0; nt < 8; nt++) {
        int c = nt * 8 + cb;
        *(float2*)&o[q0 * 64 + c] = make_float2(acc[nt][0], acc[nt][1]);
        *(float2*)&o[q1 * 64 + c] = make_float2(acc[nt][2], acc[nt][3]);
    }
}

extern "C" void kernel_launch(void* const* d_in, const int* in_sizes, int n_in,
                              void* d_out, int out_size)
{
    const float* C          = (const float*)d_in[0];   // [H, NH, 2]
    const float* log_dt     = (const float*)d_in[1];   // [H]
    const float* log_A_real = (const float*)d_in[2];   // [H, NH]
    const float* A_imag     = (const float*)d_in[3];   // [H, NH]
    float* out              = (float*)d_out;           // [H, L]

    s4_hmma_kernel<<<Hh, 128>>>(C, log_dt, log_A_real, A_imag, out);
}